// round 3
// baseline (speedup 1.0000x reference)
#include <cuda_runtime.h>
#include <math.h>

// CPABActivationDifferent: out[n][c] = cpab_transform(x[n][c]; theta[c])
// The argsort/unsort in the reference is value-identity; the transform is a
// pure elementwise map with per-(channel, cell) affine coefficients.
//
// B_BASIS reproduction: numpy.linalg.svd -> dgesdd, M=17 < N=32, N >= MNTHR(31)
// => Path "N>>M, JOBZ='A'": rows 17..31 (0-based) of Vt are rows 17..31 of the
// full Q from the LQ factorization (dgelq2 unblocked + dorgl2). We reimplement
// exactly that Householder sequence in fp64.

#define NCELL 16
#define CH 256
#define LROWS 17
#define LCOLS 32
#define NNULL 15

__device__ float2 g_eg[NCELL * CH];   // (eta, gamma) per (cell, channel)
__device__ float2 g_ab[NCELL * CH];   // (a, b) per (cell, channel)
__device__ float  g_scal[2];          // [0] = ddt

__device__ __forceinline__ float decode_time(const void* tptr) {
    // time may arrive as int32/int64 (value 1) or float32. Heuristic decode.
    int iv = *(const int*)tptr;
    float fv = __int_as_float(iv);
    float af = fabsf(fv);
    if (af >= 1e-6f && af <= 1e6f) return fv;
    return (float)iv;
}

__device__ __forceinline__ double warp_sum(double v) {
    #pragma unroll
    for (int off = 16; off; off >>= 1)
        v += __shfl_xor_sync(0xffffffffu, v, off);
    return v;
}

// ---------------------------------------------------------------------------
// Precompute: LAPACK-faithful null basis + per-channel coefficient tables.
// One block, 512 threads (16 warps). Lane = column index (0..31).
// ---------------------------------------------------------------------------
__global__ void cpab_precompute_kernel(const float* __restrict__ theta,
                                       const void* __restrict__ timep) {
    __shared__ double sM[LROWS][LCOLS];
    __shared__ double stau[LROWS];
    __shared__ double sQ[NNULL][LCOLS];

    const int tid  = threadIdx.x;
    const int lane = tid & 31;
    const int w    = tid >> 5;

    // Build constraint matrix L (17x32), fp64.
    for (int i = tid; i < LROWS * LCOLS; i += blockDim.x)
        ((double*)sM)[i] = 0.0;
    __syncthreads();
    if (tid == 0) {
        for (int k = 1; k < NCELL; k++) {
            double xk = (double)k / (double)NCELL;
            sM[k - 1][2 * (k - 1)]     =  xk;
            sM[k - 1][2 * (k - 1) + 1] =  1.0;
            sM[k - 1][2 * k]           = -xk;
            sM[k - 1][2 * k + 1]       = -1.0;
        }
        sM[NCELL - 1][1] = 1.0;               // b_0 = 0
        sM[NCELL][2 * NCELL - 2] = 1.0;       // a_15 + b_15 = 0
        sM[NCELL][2 * NCELL - 1] = 1.0;
    }
    __syncthreads();

    // dgelq2: unblocked Householder LQ, LAPACK conventions.
    for (int i = 0; i < LROWS; i++) {
        if (w == 0) {
            double aij = sM[i][lane];
            double sq  = (lane > i) ? aij * aij : 0.0;
            sq = warp_sum(sq);
            double alpha = __shfl_sync(0xffffffffu, aij, i);
            double xnorm = sqrt(sq);
            double tau = 0.0;
            if (xnorm != 0.0) {
                // dlapy2(alpha, xnorm)
                double aa = fabs(alpha);
                double wv = fmax(aa, xnorm), zv = fmin(aa, xnorm);
                double r  = (zv == 0.0) ? wv : wv * sqrt(1.0 + (zv / wv) * (zv / wv));
                double beta = (alpha >= 0.0) ? -r : r;   // -SIGN(r, alpha)
                tau = (beta - alpha) / beta;
                double inv = 1.0 / (alpha - beta);
                if (lane > i)  sM[i][lane] = aij * inv;  // reflector tail v
                if (lane == i) sM[i][i] = beta;
            }
            if (lane == 0) stau[i] = tau;
        }
        __syncthreads();
        // Apply H(i) from the right to rows i+1..16 (warp per row).
        int r = i + 1 + w;
        if (r < LROWS) {
            double tau = stau[i];
            if (tau != 0.0) {
                double v   = (lane == i) ? 1.0 : ((lane > i) ? sM[i][lane] : 0.0);
                double arj = (lane >= i) ? sM[r][lane] : 0.0;
                double dot = warp_sum(arj * v);
                if (lane >= i) sM[r][lane] = arj - tau * dot * v;
            }
        }
        __syncthreads();
    }

    // dorgl2 for rows 17..31 of Q: q_r = e_r, apply H(16)..H(0) from the right.
    if (w < NNULL) {
        int r = LROWS + w;
        double q = (lane == r) ? 1.0 : 0.0;
        for (int i = LROWS - 1; i >= 0; i--) {
            double tau = stau[i];
            double v = (lane == i) ? 1.0 : ((lane > i) ? sM[i][lane] : 0.0);
            double dot = warp_sum(q * v);
            q -= tau * dot * v;
        }
        sQ[w][lane] = q;
    }
    __syncthreads();

    // Per-channel tables. B[j][cc] = sQ[cc][j]; A[c][j] = sum_cc theta[c][cc]*sQ[cc][j].
    if (tid < CH) {
        const int c = tid;
        float tf  = decode_time(timep);
        float dt  = tf / 10.0f;      // time / NSTEPS1
        float ddt = dt / 5.0f;       // dt / NSTEPS2
        float A[LCOLS];
        #pragma unroll
        for (int j = 0; j < LCOLS; j++) {
            float s = 0.0f;
            #pragma unroll
            for (int cc = 0; cc < NNULL; cc++)
                s += theta[c * NNULL + cc] * (float)sQ[cc][j];
            A[j] = s;
        }
        #pragma unroll
        for (int k = 0; k < NCELL; k++) {
            float a = A[2 * k], b = A[2 * k + 1];
            float eta, gam;
            if (fabsf(a) > 1e-7f) {
                eta = expf(dt * a);
                gam = __fmul_rn(__fdiv_rn(b, a), __fsub_rn(eta, 1.0f));
            } else {
                eta = 1.0f;
                gam = __fmul_rn(b, dt);
            }
            g_eg[k * CH + c] = make_float2(eta, gam);
            g_ab[k * CH + c] = make_float2(a, b);
        }
        if (tid == 0) g_scal[0] = ddt;
    }
}

// ---------------------------------------------------------------------------
// Main elementwise transform.
// ---------------------------------------------------------------------------
__device__ __forceinline__ int cell_of(float v) {
    int ci = (int)floorf(__fmul_rn(v, 16.0f));
    ci = ci < 0 ? 0 : ci;
    return ci > 15 ? 15 : ci;
}

__global__ void __launch_bounds__(512, 3)
cpab_main_kernel(const float* __restrict__ x,
                 const float* __restrict__ theta,
                 float* __restrict__ out,
                 long long n, int ntheta) {
    extern __shared__ float2 sh[];
    float2* s_eg = sh;
    float2* s_ab = sh + NCELL * CH;

    for (int i = threadIdx.x; i < NCELL * CH; i += blockDim.x) {
        s_eg[i] = g_eg[i];
        s_ab[i] = g_ab[i];
    }
    const float ddt = g_scal[0];
    __syncthreads();

    const long long stride = (long long)gridDim.x * blockDim.x;
    const long long i0 = (long long)blockIdx.x * blockDim.x + threadIdx.x;

    // theta passthrough tail
    for (long long t = i0; t < ntheta; t += stride)
        out[n + t] = theta[t];

    long long i = i0;
    float xv = (i < n) ? __ldg(x + i) : 0.0f;
    while (i < n) {
        long long inext = i + stride;
        float xnext = (inext < n) ? __ldg(x + inext) : 0.0f;

        const int c = (int)(i & (CH - 1));
        float s = __fdiv_rn(__fadd_rn(xv, 3.0f), 6.0f);
        float res;
        if (s >= 1.0f || s <= 0.0f) {
            res = xv;  // out-of-domain passthrough
        } else {
            float p = s;
            #pragma unroll 1
            for (int step = 0; step < 10; ++step) {
                int c0 = cell_of(p);
                float2 eg = s_eg[(c0 << 8) + c];
                float pcf = __fadd_rn(__fmul_rn(eg.x, p), eg.y);
                if (cell_of(pcf) == c0) {
                    p = pcf;
                } else {
                    #pragma unroll
                    for (int ss = 0; ss < 5; ++ss) {
                        int cc = cell_of(p);
                        float2 ab = s_ab[(cc << 8) + c];
                        float v = __fadd_rn(__fmul_rn(ab.x, p), ab.y);
                        p = __fadd_rn(p, __fmul_rn(ddt, v));
                    }
                }
            }
            res = __fsub_rn(__fmul_rn(p, 6.0f), 3.0f);
        }
        out[i] = res;
        i = inext;
        xv = xnext;
    }
}

extern "C" void kernel_launch(void* const* d_in, const int* in_sizes, int n_in,
                              void* d_out, int out_size) {
    const float* x      = (const float*)d_in[0];
    // d_in[1] edge_index, d_in[2] edge_attr, d_in[3] batch: unused
    const void*  timep  = d_in[4];
    const float* theta  = (const float*)d_in[5];
    float* out = (float*)d_out;

    const long long n = (long long)in_sizes[0];
    const int ntheta = out_size - (int)n;

    cpab_precompute_kernel<<<1, 512>>>(theta, timep);

    static bool attr_set = false;
    // cudaFuncSetAttribute is idempotent and executes immediately (not a
    // stream op) — safe under graph capture; call every time for determinism.
    cudaFuncSetAttribute(cpab_main_kernel,
                         cudaFuncAttributeMaxDynamicSharedMemorySize,
                         (int)(2 * NCELL * CH * sizeof(float2)));
    (void)attr_set;

    const int threads = 512;
    const int blocks = 456;  // 152 SMs * 3 (64KB smem each)
    const size_t smem = 2 * NCELL * CH * sizeof(float2);
    cpab_main_kernel<<<blocks, threads, smem>>>(x, theta, out, n, ntheta);
}